// round 6
// baseline (speedup 1.0000x reference)
#include <cuda_runtime.h>
#include <math.h>
#include <stdint.h>

// Problem constants
#define TOK   8192
#define DDIM  1024
#define FDIM  2048
#define NEXP  8
#define TOPK  2

#define BK    16
#define PBS1  68     // B pair-row stride (gemm1, BN=64)
#define PBS2  132    // B pair-row stride (gemm2, BN=128)

// ---------------------------------------------------------------------------
// Scratch
// ---------------------------------------------------------------------------
__device__ int   g_count[NEXP];
__device__ int   g_rows [NEXP * TOK];
__device__ int   g_slot [NEXP * TOK];
__device__ float g_gate [TOK * TOPK];
__device__ float g_H    [(size_t)NEXP * TOK * FDIM];
__device__ float g_Y    [(size_t)TOK * TOPK * DDIM];

// ---------------------------------------------------------------------------
// tf32 helpers
// ---------------------------------------------------------------------------
__device__ __forceinline__ uint32_t f2tf32(float f) {
    uint32_t u;
    asm("cvt.rna.tf32.f32 %0, %1;" : "=r"(u) : "f"(f));
    return u;
}

__device__ __forceinline__ void mma4(float c[4], const uint4& a,
                                     uint32_t b0, uint32_t b1) {
    asm volatile(
        "mma.sync.aligned.m16n8k8.row.col.f32.tf32.tf32.f32 "
        "{%0,%1,%2,%3}, {%4,%5,%6,%7}, {%8,%9}, {%0,%1,%2,%3};"
        : "+f"(c[0]), "+f"(c[1]), "+f"(c[2]), "+f"(c[3])
        : "r"(a.x), "r"(a.y), "r"(a.z), "r"(a.w), "r"(b0), "r"(b1));
}

// Permuted A layout: fragment-order storage, swizzled.
__device__ __forceinline__ int a_off(int tm, int tk, int L, int comp) {
    int slot = ((L & ~3) | ((L & 3) ^ ((L >> 2) & 3))) ^ ((tm & 1) << 2);
    return ((tm * 2 + tk) * 32 + slot) * 4 + comp;
}

__device__ __forceinline__ void a_store(uint32_t* As, int row, int k, float v) {
    const int tm = row >> 4, r16 = row & 15;
    const int L = (r16 & 7) * 4 + (k & 3);
    const int comp = (r16 >> 3) + (((k >> 2) & 1) << 1);
    As[a_off(tm, k >> 3, L, comp)] = f2tf32(v);
}

// ---------------------------------------------------------------------------
// 0) zero expert counters
// ---------------------------------------------------------------------------
__global__ void zero_counts_kernel() {
    if (threadIdx.x < NEXP) g_count[threadIdx.x] = 0;
}

// ---------------------------------------------------------------------------
// 1) Router (one warp per token)
// ---------------------------------------------------------------------------
__global__ __launch_bounds__(256) void router_kernel(const float* __restrict__ x,
                                                     const float* __restrict__ Wg) {
    const int warp = (blockIdx.x * blockDim.x + threadIdx.x) >> 5;
    const int lane = threadIdx.x & 31;
    if (warp >= TOK) return;

    const float* xr = x + (size_t)warp * DDIM;
    float acc[NEXP];
#pragma unroll
    for (int e = 0; e < NEXP; e++) acc[e] = 0.f;

    for (int d = lane; d < DDIM; d += 32) {
        const float xv = xr[d];
        const float4 w0 = *reinterpret_cast<const float4*>(Wg + (size_t)d * NEXP);
        const float4 w1 = *reinterpret_cast<const float4*>(Wg + (size_t)d * NEXP + 4);
        acc[0] += xv * w0.x; acc[1] += xv * w0.y; acc[2] += xv * w0.z; acc[3] += xv * w0.w;
        acc[4] += xv * w1.x; acc[5] += xv * w1.y; acc[6] += xv * w1.z; acc[7] += xv * w1.w;
    }
#pragma unroll
    for (int off = 16; off > 0; off >>= 1) {
#pragma unroll
        for (int e = 0; e < NEXP; e++)
            acc[e] += __shfl_xor_sync(0xFFFFFFFFu, acc[e], off);
    }

    if (lane == 0) {
        int i0 = 0; float v0 = acc[0];
#pragma unroll
        for (int e = 1; e < NEXP; e++) if (acc[e] > v0) { v0 = acc[e]; i0 = e; }
        int i1 = -1; float v1 = -INFINITY;
#pragma unroll
        for (int e = 0; e < NEXP; e++)
            if (e != i0 && acc[e] > v1) { v1 = acc[e]; i1 = e; }

        const float e1 = expf(v1 - v0);
        const float inv = 1.f / (1.f + e1);
        g_gate[warp * 2 + 0] = inv;
        g_gate[warp * 2 + 1] = e1 * inv;

        int p0 = atomicAdd(&g_count[i0], 1);
        g_rows[i0 * TOK + p0] = warp;
        g_slot[i0 * TOK + p0] = warp * 2;
        int p1 = atomicAdd(&g_count[i1], 1);
        g_rows[i1 * TOK + p1] = warp;
        g_slot[i1 * TOK + p1] = warp * 2 + 1;
    }
}

// ---------------------------------------------------------------------------
// 2) Grouped dual GEMM + SwiGLU. Block 256x64, warp 64x32 dual, 2-stage pipe.
// ---------------------------------------------------------------------------
__global__ __launch_bounds__(256, 1) void gemm1_kernel(const float* __restrict__ x,
                                                       const float* __restrict__ W1,
                                                       const float* __restrict__ W3) {
    const int e   = blockIdx.y >> 5;
    const int mt  = blockIdx.y & 31;
    const int cnt = g_count[e];
    const int m0  = mt * 256;
    if (m0 >= cnt) return;
    const int n0 = blockIdx.x * 64;

    __shared__ uint32_t As [2][4096];
    __shared__ uint32_t B1s[2][8 * PBS1 * 2];
    __shared__ uint32_t B3s[2][8 * PBS1 * 2];

    const int tid  = threadIdx.x;
    const int warp = tid >> 5;
    const int lane = tid & 31;
    const int wm = warp >> 1;
    const int wn = warp & 1;
    const int g  = lane >> 2;
    const int t  = lane & 3;

    const bool av  = (m0 + tid < cnt);
    const int  tok = av ? g_rows[e * TOK + m0 + tid] : 0;
    const float* pA = x + (size_t)tok * DDIM;

    const int kq = warp;
    const int r0 = (kq >> 2) * 8 + (kq & 3);
    const int r1 = r0 + 4;
    const float* pB1 = W1 + (size_t)e * DDIM * FDIM + n0;
    const float* pB3 = W3 + (size_t)e * DDIM * FDIM + n0;

    float acc1[4][4][4], acc3[4][4][4];
#pragma unroll
    for (int i = 0; i < 4; i++)
#pragma unroll
        for (int j = 0; j < 4; j++)
#pragma unroll
            for (int r = 0; r < 4; r++) { acc1[i][j][r] = 0.f; acc3[i][j][r] = 0.f; }

    float4 aq[4];
    float b1v[4], b3v[4];

    // prefetch k0 = 0 and fill buffer 0
    {
#pragma unroll
        for (int q = 0; q < 4; q++)
            aq[q] = *reinterpret_cast<const float4*>(pA + q * 4);
        const float* b1r0 = pB1 + (size_t)r0 * FDIM;
        const float* b1r1 = pB1 + (size_t)r1 * FDIM;
        const float* b3r0 = pB3 + (size_t)r0 * FDIM;
        const float* b3r1 = pB3 + (size_t)r1 * FDIM;
        b1v[0] = b1r0[lane]; b1v[1] = b1r0[lane + 32];
        b1v[2] = b1r1[lane]; b1v[3] = b1r1[lane + 32];
        b3v[0] = b3r0[lane]; b3v[1] = b3r0[lane + 32];
        b3v[2] = b3r1[lane]; b3v[3] = b3r1[lane + 32];

#pragma unroll
        for (int q = 0; q < 4; q++) {
            a_store(As[0], tid, q * 4 + 0, aq[q].x);
            a_store(As[0], tid, q * 4 + 1, aq[q].y);
            a_store(As[0], tid, q * 4 + 2, aq[q].z);
            a_store(As[0], tid, q * 4 + 3, aq[q].w);
        }
        *reinterpret_cast<uint2*>(&B1s[0][(kq * PBS1 + lane) * 2]) =
            make_uint2(f2tf32(b1v[0]), f2tf32(b1v[2]));
        *reinterpret_cast<uint2*>(&B1s[0][(kq * PBS1 + lane + 32) * 2]) =
            make_uint2(f2tf32(b1v[1]), f2tf32(b1v[3]));
        *reinterpret_cast<uint2*>(&B3s[0][(kq * PBS1 + lane) * 2]) =
            make_uint2(f2tf32(b3v[0]), f2tf32(b3v[2]));
        *reinterpret_cast<uint2*>(&B3s[0][(kq * PBS1 + lane + 32) * 2]) =
            make_uint2(f2tf32(b3v[1]), f2tf32(b3v[3]));
    }
    __syncthreads();

    int p = 0;
    for (int k0 = 0; k0 < DDIM; k0 += BK) {
        const bool has_next = (k0 + BK < DDIM);
        // prefetch next tile into regs (latency hidden under MMAs)
        if (has_next) {
            const int kn = k0 + BK;
#pragma unroll
            for (int q = 0; q < 4; q++)
                aq[q] = *reinterpret_cast<const float4*>(pA + kn + q * 4);
            const float* b1r0 = pB1 + (size_t)(kn + r0) * FDIM;
            const float* b1r1 = pB1 + (size_t)(kn + r1) * FDIM;
            const float* b3r0 = pB3 + (size_t)(kn + r0) * FDIM;
            const float* b3r1 = pB3 + (size_t)(kn + r1) * FDIM;
            b1v[0] = b1r0[lane]; b1v[1] = b1r0[lane + 32];
            b1v[2] = b1r1[lane]; b1v[3] = b1r1[lane + 32];
            b3v[0] = b3r0[lane]; b3v[1] = b3r0[lane + 32];
            b3v[2] = b3r1[lane]; b3v[3] = b3r1[lane + 32];
        }

        // MMAs from buffer p
#pragma unroll
        for (int ks = 0; ks < 2; ks++) {
            uint4 af[4];
#pragma unroll
            for (int i = 0; i < 4; i++) {
                const int tm = wm * 4 + i;
                af[i] = *reinterpret_cast<const uint4*>(&As[p][a_off(tm, ks, lane, 0)]);
            }
#pragma unroll
            for (int j = 0; j < 4; j++) {
                const int col = wn * 32 + j * 8 + g;
                const uint2 p1 = *reinterpret_cast<const uint2*>(
                    &B1s[p][((ks * 4 + t) * PBS1 + col) * 2]);
                const uint2 p3 = *reinterpret_cast<const uint2*>(
                    &B3s[p][((ks * 4 + t) * PBS1 + col) * 2]);
#pragma unroll
                for (int i = 0; i < 4; i++) {
                    mma4(acc1[i][j], af[i], p1.x, p1.y);
                    mma4(acc3[i][j], af[i], p3.x, p3.y);
                }
            }
        }

        // store prefetched regs into the other buffer
        if (has_next) {
            const int q1 = p ^ 1;
#pragma unroll
            for (int q = 0; q < 4; q++) {
                a_store(As[q1], tid, q * 4 + 0, aq[q].x);
                a_store(As[q1], tid, q * 4 + 1, aq[q].y);
                a_store(As[q1], tid, q * 4 + 2, aq[q].z);
                a_store(As[q1], tid, q * 4 + 3, aq[q].w);
            }
            *reinterpret_cast<uint2*>(&B1s[q1][(kq * PBS1 + lane) * 2]) =
                make_uint2(f2tf32(b1v[0]), f2tf32(b1v[2]));
            *reinterpret_cast<uint2*>(&B1s[q1][(kq * PBS1 + lane + 32) * 2]) =
                make_uint2(f2tf32(b1v[1]), f2tf32(b1v[3]));
            *reinterpret_cast<uint2*>(&B3s[q1][(kq * PBS1 + lane) * 2]) =
                make_uint2(f2tf32(b3v[0]), f2tf32(b3v[2]));
            *reinterpret_cast<uint2*>(&B3s[q1][(kq * PBS1 + lane + 32) * 2]) =
                make_uint2(f2tf32(b3v[1]), f2tf32(b3v[3]));
            __syncthreads();
        }
        p ^= 1;
    }

    float* Hbase = g_H + (size_t)e * TOK * FDIM;
    const int lim = cnt - m0;
#pragma unroll
    for (int i = 0; i < 4; i++) {
        const int lrow0 = wm * 64 + i * 16 + g;
        const int lrow1 = lrow0 + 8;
#pragma unroll
        for (int j = 0; j < 4; j++) {
            const int col = n0 + wn * 32 + j * 8 + 2 * t;
            if (lrow0 < lim) {
                const float z0 = acc1[i][j][0], z1 = acc1[i][j][1];
                float2 hv;
                hv.x = (z0 / (1.f + expf(-z0))) * acc3[i][j][0];
                hv.y = (z1 / (1.f + expf(-z1))) * acc3[i][j][1];
                *reinterpret_cast<float2*>(Hbase + (size_t)(m0 + lrow0) * FDIM + col) = hv;
            }
            if (lrow1 < lim) {
                const float z2 = acc1[i][j][2], z3 = acc1[i][j][3];
                float2 hv;
                hv.x = (z2 / (1.f + expf(-z2))) * acc3[i][j][2];
                hv.y = (z3 / (1.f + expf(-z3))) * acc3[i][j][3];
                *reinterpret_cast<float2*>(Hbase + (size_t)(m0 + lrow1) * FDIM + col) = hv;
            }
        }
    }
}

// ---------------------------------------------------------------------------
// 3) Grouped GEMM2. Block 256x128, warp 64x64, 2-stage pipe.
// ---------------------------------------------------------------------------
__global__ __launch_bounds__(256, 1) void gemm2_kernel(const float* __restrict__ W2) {
    const int e   = blockIdx.y >> 5;
    const int mt  = blockIdx.y & 31;
    const int cnt = g_count[e];
    const int m0  = mt * 256;
    if (m0 >= cnt) return;
    const int n0 = blockIdx.x * 128;

    __shared__ uint32_t As[2][4096];
    __shared__ uint32_t Bs[2][8 * PBS2 * 2];

    const int tid  = threadIdx.x;
    const int warp = tid >> 5;
    const int lane = tid & 31;
    const int wm = warp >> 1;
    const int wn = warp & 1;
    const int g  = lane >> 2;
    const int t  = lane & 3;

    const float* pA = g_H + ((size_t)e * TOK + (m0 + tid)) * FDIM;

    const int kq = warp;
    const int r0 = (kq >> 2) * 8 + (kq & 3);
    const int r1 = r0 + 4;
    const float* pB = W2 + (size_t)e * FDIM * DDIM + n0;

    float acc[4][8][4];
#pragma unroll
    for (int i = 0; i < 4; i++)
#pragma unroll
        for (int j = 0; j < 8; j++)
#pragma unroll
            for (int r = 0; r < 4; r++) acc[i][j][r] = 0.f;

    float4 aq[4];
    float bv[8];

    {
#pragma unroll
        for (int q = 0; q < 4; q++)
            aq[q] = *reinterpret_cast<const float4*>(pA + q * 4);
        const float* br0 = pB + (size_t)r0 * DDIM;
        const float* br1 = pB + (size_t)r1 * DDIM;
#pragma unroll
        for (int c = 0; c < 4; c++) {
            bv[c]     = br0[lane + c * 32];
            bv[4 + c] = br1[lane + c * 32];
        }
#pragma unroll
        for (int q = 0; q < 4; q++) {
            a_store(As[0], tid, q * 4 + 0, aq[q].x);
            a_store(As[0], tid, q * 4 + 1, aq[q].y);
            a_store(As[0], tid, q * 4 + 2, aq[q].z);
            a_store(As[0], tid, q * 4 + 3, aq[q].w);
        }
#pragma unroll
        for (int c = 0; c < 4; c++)
            *reinterpret_cast<uint2*>(&Bs[0][(kq * PBS2 + lane + c * 32) * 2]) =
                make_uint2(f2tf32(bv[c]), f2tf32(bv[4 + c]));
    }
    __syncthreads();

    int p = 0;
    for (int k0 = 0; k0 < FDIM; k0 += BK) {
        const bool has_next = (k0 + BK < FDIM);
        if (has_next) {
            const int kn = k0 + BK;
#pragma unroll
            for (int q = 0; q < 4; q++)
                aq[q] = *reinterpret_cast<const float4*>(pA + kn + q * 4);
            const float* br0 = pB + (size_t)(kn + r0) * DDIM;
            const float* br1 = pB + (size_t)(kn + r1) * DDIM;
#pragma unroll
            for (int c = 0; c < 4; c++) {
                bv[c]     = br0[lane + c * 32];
                bv[4 + c] = br1[lane + c * 32];
            }
        }

#pragma unroll
        for (int ks = 0; ks < 2; ks++) {
            uint4 af[4];
#pragma unroll
            for (int i = 0; i < 4; i++) {
                const int tm = wm * 4 + i;
                af[i] = *reinterpret_cast<const uint4*>(&As[p][a_off(tm, ks, lane, 0)]);
            }
#pragma unroll
            for (int j = 0; j < 8; j++) {
                const int col = wn * 64 + j * 8 + g;
                const uint2 pr = *reinterpret_cast<const uint2*>(
                    &Bs[p][((ks * 4 + t) * PBS2 + col) * 2]);
#pragma unroll
                for (int i = 0; i < 4; i++)
                    mma4(acc[i][j], af[i], pr.x, pr.y);
            }
        }

        if (has_next) {
            const int q1 = p ^ 1;
#pragma unroll
            for (int q = 0; q < 4; q++) {
                a_store(As[q1], tid, q * 4 + 0, aq[q].x);
                a_store(As[q1], tid, q * 4 + 1, aq[q].y);
                a_store(As[q1], tid, q * 4 + 2, aq[q].z);
                a_store(As[q1], tid, q * 4 + 3, aq[q].w);
            }
#pragma unroll
            for (int c = 0; c < 4; c++)
                *reinterpret_cast<uint2*>(&Bs[q1][(kq * PBS2 + lane + c * 32) * 2]) =
                    make_uint2(f2tf32(bv[c]), f2tf32(bv[4 + c]));
            __syncthreads();
        }
        p ^= 1;
    }

    const int lim = cnt - m0;
#pragma unroll
    for (int i = 0; i < 4; i++) {
        const int lrow0 = wm * 64 + i * 16 + g;
        const int lrow1 = lrow0 + 8;
        const int slot0 = (lrow0 < lim) ? g_slot[e * TOK + m0 + lrow0] : -1;
        const int slot1 = (lrow1 < lim) ? g_slot[e * TOK + m0 + lrow1] : -1;
#pragma unroll
        for (int j = 0; j < 8; j++) {
            const int col = n0 + wn * 64 + j * 8 + 2 * t;
            if (slot0 >= 0)
                *reinterpret_cast<float2*>(g_Y + (size_t)slot0 * DDIM + col) =
                    make_float2(acc[i][j][0], acc[i][j][1]);
            if (slot1 >= 0)
                *reinterpret_cast<float2*>(g_Y + (size_t)slot1 * DDIM + col) =
                    make_float2(acc[i][j][2], acc[i][j][3]);
        }
    }
}

// ---------------------------------------------------------------------------
// 4) Combine
// ---------------------------------------------------------------------------
__global__ __launch_bounds__(256) void combine_kernel(float* __restrict__ out) {
    const int tk = blockIdx.x;
    const int d = threadIdx.x * 4;
    const float g0 = g_gate[tk * 2 + 0];
    const float g1 = g_gate[tk * 2 + 1];
    const float4 y0 = *reinterpret_cast<const float4*>(g_Y + ((size_t)tk * 2 + 0) * DDIM + d);
    const float4 y1 = *reinterpret_cast<const float4*>(g_Y + ((size_t)tk * 2 + 1) * DDIM + d);
    float4 o;
    o.x = g0 * y0.x + g1 * y1.x;
    o.y = g0 * y0.y + g1 * y1.y;
    o.z = g0 * y0.z + g1 * y1.z;
    o.w = g0 * y0.w + g1 * y1.w;
    *reinterpret_cast<float4*>(out + (size_t)tk * DDIM + d) = o;
}

// ---------------------------------------------------------------------------
// Entry
// ---------------------------------------------------------------------------
extern "C" void kernel_launch(void* const* d_in, const int* in_sizes, int n_in,
                              void* d_out, int out_size) {
    const float* x  = (const float*)d_in[0];
    const float* Wg = (const float*)d_in[1];
    const float* W1 = (const float*)d_in[2];
    const float* W3 = (const float*)d_in[3];
    const float* W2 = (const float*)d_in[4];
    float* out = (float*)d_out;

    zero_counts_kernel<<<1, 32>>>();
    router_kernel<<<TOK / 8, 256>>>(x, Wg);
    gemm1_kernel<<<dim3(FDIM / 64, NEXP * (TOK / 256)), 256>>>(x, W1, W3);
    gemm2_kernel<<<dim3(DDIM / 128, NEXP * (TOK / 256)), 256>>>(W2);
    combine_kernel<<<TOK, 256>>>(out);
}